// round 1
// baseline (speedup 1.0000x reference)
#include <cuda_runtime.h>
#include <cuda_bf16.h>
#include <math.h>

// Problem: T=2048 tokens, H=2048 hidden, V=32000 vocab, E=16 experts, top-2.
// Inputs (metadata order): hidden_states (T*H f32), gate_w (16*H f32),
// expert_biases (16*V f32). Output: bias (T*V f32) then aux_loss (1 f32).

#define NUM_E 16
#define MAX_T 8192

// Scratch (device globals; no allocation allowed)
__device__ float  g_probs[MAX_T * NUM_E];   // softmax probs per token
__device__ float4 g_meta[MAX_T];            // (w0, w1, bitcast i0, bitcast i1)

// ---------------------------------------------------------------------------
// Kernel 1: gate logits + softmax + top-2. One block = 16 tokens, 4 passes of
// 4 tokens. gate_w read via __ldg (131KB, L1/L2 resident); each gw float4 is
// reused across 4 tokens in registers to cut L1 traffic 4x.
// ---------------------------------------------------------------------------
__global__ __launch_bounds__(256) void gate_kernel(
    const float* __restrict__ hidden,
    const float* __restrict__ gate_w,
    int H)
{
    const int tid  = threadIdx.x;
    const int lane = tid & 31;
    const int warp = tid >> 5;
    const int Hf4  = H >> 2;

    const float4* __restrict__ hf4 = (const float4*)hidden;
    const float4* __restrict__ gf4 = (const float4*)gate_w;

    __shared__ float red[8][NUM_E][4];   // per-warp partials
    __shared__ float slog[4][NUM_E];     // logits for the 4 tokens of a pass

    for (int pass = 0; pass < 4; pass++) {
        const int t0 = blockIdx.x * 16 + pass * 4;  // first token of pass

        float acc[NUM_E][4];
        #pragma unroll
        for (int e = 0; e < NUM_E; e++)
            #pragma unroll
            for (int t = 0; t < 4; t++) acc[e][t] = 0.0f;

        for (int i = tid; i < Hf4; i += 256) {
            float4 h0 = hf4[(size_t)(t0 + 0) * Hf4 + i];
            float4 h1 = hf4[(size_t)(t0 + 1) * Hf4 + i];
            float4 h2 = hf4[(size_t)(t0 + 2) * Hf4 + i];
            float4 h3 = hf4[(size_t)(t0 + 3) * Hf4 + i];
            #pragma unroll
            for (int e = 0; e < NUM_E; e++) {
                float4 g = __ldg(&gf4[(size_t)e * Hf4 + i]);
                acc[e][0] += h0.x*g.x + h0.y*g.y + h0.z*g.z + h0.w*g.w;
                acc[e][1] += h1.x*g.x + h1.y*g.y + h1.z*g.z + h1.w*g.w;
                acc[e][2] += h2.x*g.x + h2.y*g.y + h2.z*g.z + h2.w*g.w;
                acc[e][3] += h3.x*g.x + h3.y*g.y + h3.z*g.z + h3.w*g.w;
            }
        }

        // warp butterfly reduction (deterministic)
        #pragma unroll
        for (int e = 0; e < NUM_E; e++) {
            #pragma unroll
            for (int t = 0; t < 4; t++) {
                float v = acc[e][t];
                v += __shfl_xor_sync(0xffffffffu, v, 16);
                v += __shfl_xor_sync(0xffffffffu, v, 8);
                v += __shfl_xor_sync(0xffffffffu, v, 4);
                v += __shfl_xor_sync(0xffffffffu, v, 2);
                v += __shfl_xor_sync(0xffffffffu, v, 1);
                if (lane == 0) red[warp][e][t] = v;
            }
        }
        __syncthreads();

        // combine the 8 warp partials (deterministic fixed order)
        if (tid < 64) {
            int e = tid >> 2, t = tid & 3;
            float s = 0.0f;
            #pragma unroll
            for (int w = 0; w < 8; w++) s += red[w][e][t];
            slog[t][e] = s;
        }
        __syncthreads();

        // per-token softmax + top-2 by one thread each
        if (tid < 4) {
            const int tok = t0 + tid;
            float l[NUM_E];
            float mx = -1e30f;
            #pragma unroll
            for (int e = 0; e < NUM_E; e++) { l[e] = slog[tid][e]; mx = fmaxf(mx, l[e]); }
            float sum = 0.0f;
            float p[NUM_E];
            #pragma unroll
            for (int e = 0; e < NUM_E; e++) { p[e] = expf(l[e] - mx); sum += p[e]; }
            float inv = 1.0f / sum;
            int   i0 = 0, i1 = -1;
            float p0 = -1.0f, p1 = -1.0f;
            #pragma unroll
            for (int e = 0; e < NUM_E; e++) {
                float pe = p[e] * inv;
                g_probs[(size_t)tok * NUM_E + e] = pe;
                if (pe > p0)      { p1 = p0; i1 = i0; p0 = pe; i0 = e; }
                else if (pe > p1) { p1 = pe; i1 = e; }
            }
            float s2 = p0 + p1;
            float4 m;
            m.x = p0 / s2;
            m.y = p1 / s2;
            m.z = __int_as_float(i0);
            m.w = __int_as_float(i1);
            g_meta[tok] = m;
        }
        __syncthreads();
    }
}

// ---------------------------------------------------------------------------
// Kernel 2: aux loss. Single block, deterministic reduction.
// ---------------------------------------------------------------------------
__global__ __launch_bounds__(256) void aux_kernel(float* __restrict__ out_aux, int T)
{
    __shared__ float s[256];
    __shared__ float su[NUM_E];
    const int tid = threadIdx.x;
    const int e = tid & 15;
    const int c = tid >> 4;      // 16 chunks

    float sum = 0.0f;
    for (int t = c; t < T; t += 16)
        sum += g_probs[(size_t)t * NUM_E + e];
    s[tid] = sum;
    __syncthreads();

    if (tid < NUM_E) {
        float u = 0.0f;
        #pragma unroll
        for (int cc = 0; cc < 16; cc++) u += s[cc * 16 + tid];
        su[tid] = u;
    }
    __syncthreads();

    if (tid == 0) {
        float aux = 0.0f;
        float invT = 1.0f / (float)T;
        #pragma unroll
        for (int ee = 0; ee < NUM_E; ee++) {
            float u = su[ee] * invT;
            aux += u * logf(u);
        }
        out_aux[0] = aux * (float)NUM_E;
    }
}

// ---------------------------------------------------------------------------
// Kernel 3: bias = w0*B[i0] + w1*B[i1], write-bound (262 MB stores).
// Block = (v-chunk of 500 floats, group of 64 tokens). Stage all 16 experts'
// chunk (32KB) in smem so gmem reads stay ~64 MB total (L2 hits).
// ---------------------------------------------------------------------------
#define CHUNK_F4 125          // 500 floats per expert per chunk
#define TOK_GRP  64

__global__ __launch_bounds__(256) void bias_kernel(
    const float* __restrict__ biases,
    float* __restrict__ out,
    int V)
{
    __shared__ float4 sB[NUM_E][CHUNK_F4];   // 32 KB
    __shared__ float4 smeta[TOK_GRP];

    const int tid   = threadIdx.x;
    const int Vf4   = V >> 2;
    const int vbase = blockIdx.x * CHUNK_F4;          // f4 offset within row
    const int tbase = blockIdx.y * TOK_GRP;

    const float4* __restrict__ bf4 = (const float4*)biases;
    float4* __restrict__ of4 = (float4*)out;

    for (int i = tid; i < NUM_E * CHUNK_F4; i += 256) {
        int e = i / CHUNK_F4, p = i - e * CHUNK_F4;
        sB[e][p] = bf4[(size_t)e * Vf4 + vbase + p];
    }
    if (tid < TOK_GRP) smeta[tid] = g_meta[tbase + tid];
    __syncthreads();

    for (int i = tid; i < TOK_GRP * CHUNK_F4; i += 256) {
        int t = i / CHUNK_F4, p = i - t * CHUNK_F4;
        float4 m = smeta[t];
        int i0 = __float_as_int(m.z);
        int i1 = __float_as_int(m.w);
        float4 a = sB[i0][p];
        float4 b = sB[i1][p];
        float4 r;
        r.x = m.x * a.x + m.y * b.x;
        r.y = m.x * a.y + m.y * b.y;
        r.z = m.x * a.z + m.y * b.z;
        r.w = m.x * a.w + m.y * b.w;
        of4[(size_t)(tbase + t) * Vf4 + vbase + p] = r;
    }
}

// ---------------------------------------------------------------------------
extern "C" void kernel_launch(void* const* d_in, const int* in_sizes, int n_in,
                              void* d_out, int out_size)
{
    const float* hidden = (const float*)d_in[0];
    const float* gate_w = (const float*)d_in[1];
    const float* biases = (const float*)d_in[2];
    float* out = (float*)d_out;

    const int H = in_sizes[1] / NUM_E;         // 2048
    const int T = in_sizes[0] / H;             // 2048
    const int V = in_sizes[2] / NUM_E;         // 32000

    // 1) gating: 16 tokens per block
    gate_kernel<<<T / 16, 256>>>(hidden, gate_w, H);

    // 2) aux loss -> out[T*V]
    aux_kernel<<<1, 256>>>(out + (size_t)T * V, T);

    // 3) bias gather+blend
    dim3 grid(V / (CHUNK_F4 * 4), T / TOK_GRP);   // (64, 32)
    bias_kernel<<<grid, 256>>>(biases, out, V);
}

// round 2
// speedup vs baseline: 1.0008x; 1.0008x over previous
#include <cuda_runtime.h>
#include <cuda_bf16.h>
#include <math.h>

// Problem: T=2048 tokens, H=2048 hidden, V=32000 vocab, E=16 experts, top-2.
// Inputs: hidden_states (T*H f32), gate_w (16*H f32), expert_biases (16*V f32).
// Output: bias (T*V f32) then aux_loss (1 f32).

#define NUM_E 16
#define MAX_T 8192

__device__ float  g_probs[MAX_T * NUM_E];   // softmax probs per token
__device__ float4 g_meta[MAX_T];            // (w0, w1, bitcast i0, bitcast i1)

// ---------------------------------------------------------------------------
// Kernel 1: gate logits + softmax + top-2. One block = 4 tokens, single pass.
// grid = T/4 = 512 blocks -> full chip. gate_w float4 reused across 4 tokens.
// ---------------------------------------------------------------------------
__global__ __launch_bounds__(256) void gate_kernel(
    const float* __restrict__ hidden,
    const float* __restrict__ gate_w,
    int H)
{
    const int tid  = threadIdx.x;
    const int lane = tid & 31;
    const int warp = tid >> 5;
    const int Hf4  = H >> 2;
    const int t0   = blockIdx.x * 4;

    const float4* __restrict__ hf4 = (const float4*)hidden;
    const float4* __restrict__ gf4 = (const float4*)gate_w;

    __shared__ float red[8][NUM_E][4];
    __shared__ float slog[4][NUM_E];

    float acc[NUM_E][4];
    #pragma unroll
    for (int e = 0; e < NUM_E; e++)
        #pragma unroll
        for (int t = 0; t < 4; t++) acc[e][t] = 0.0f;

    for (int i = tid; i < Hf4; i += 256) {
        float4 h0 = hf4[(size_t)(t0 + 0) * Hf4 + i];
        float4 h1 = hf4[(size_t)(t0 + 1) * Hf4 + i];
        float4 h2 = hf4[(size_t)(t0 + 2) * Hf4 + i];
        float4 h3 = hf4[(size_t)(t0 + 3) * Hf4 + i];
        #pragma unroll
        for (int e = 0; e < NUM_E; e++) {
            float4 g = __ldg(&gf4[(size_t)e * Hf4 + i]);
            acc[e][0] += h0.x*g.x + h0.y*g.y + h0.z*g.z + h0.w*g.w;
            acc[e][1] += h1.x*g.x + h1.y*g.y + h1.z*g.z + h1.w*g.w;
            acc[e][2] += h2.x*g.x + h2.y*g.y + h2.z*g.z + h2.w*g.w;
            acc[e][3] += h3.x*g.x + h3.y*g.y + h3.z*g.z + h3.w*g.w;
        }
    }

    // warp butterfly reduction (deterministic)
    #pragma unroll
    for (int e = 0; e < NUM_E; e++) {
        #pragma unroll
        for (int t = 0; t < 4; t++) {
            float v = acc[e][t];
            v += __shfl_xor_sync(0xffffffffu, v, 16);
            v += __shfl_xor_sync(0xffffffffu, v, 8);
            v += __shfl_xor_sync(0xffffffffu, v, 4);
            v += __shfl_xor_sync(0xffffffffu, v, 2);
            v += __shfl_xor_sync(0xffffffffu, v, 1);
            if (lane == 0) red[warp][e][t] = v;
        }
    }
    __syncthreads();

    if (tid < 64) {
        int e = tid >> 2, t = tid & 3;
        float s = 0.0f;
        #pragma unroll
        for (int w = 0; w < 8; w++) s += red[w][e][t];
        slog[t][e] = s;
    }
    __syncthreads();

    if (tid < 4) {
        const int tok = t0 + tid;
        float l[NUM_E];
        float mx = -1e30f;
        #pragma unroll
        for (int e = 0; e < NUM_E; e++) { l[e] = slog[tid][e]; mx = fmaxf(mx, l[e]); }
        float sum = 0.0f;
        float p[NUM_E];
        #pragma unroll
        for (int e = 0; e < NUM_E; e++) { p[e] = expf(l[e] - mx); sum += p[e]; }
        float inv = 1.0f / sum;
        int   i0 = 0, i1 = -1;
        float p0 = -1.0f, p1 = -1.0f;
        #pragma unroll
        for (int e = 0; e < NUM_E; e++) {
            float pe = p[e] * inv;
            g_probs[(size_t)tok * NUM_E + e] = pe;
            if (pe > p0)      { p1 = p0; i1 = i0; p0 = pe; i0 = e; }
            else if (pe > p1) { p1 = pe; i1 = e; }
        }
        float s2 = p0 + p1;
        float4 m;
        m.x = p0 / s2;
        m.y = p1 / s2;
        m.z = __int_as_float(i0);
        m.w = __int_as_float(i1);
        g_meta[tok] = m;
    }
}

// ---------------------------------------------------------------------------
// Kernel 2: aux loss. Single block, float4 coalesced, deterministic.
// ---------------------------------------------------------------------------
__global__ __launch_bounds__(256) void aux_kernel(float* __restrict__ out_aux, int T)
{
    __shared__ float4 s4[256];
    __shared__ float4 su4[4];
    const int tid = threadIdx.x;
    const int e4  = tid & 3;      // which group of 4 experts
    const int c   = tid >> 2;     // 64 token-chunks

    const float4* __restrict__ probs4 = (const float4*)g_probs;

    float4 sum = make_float4(0.f, 0.f, 0.f, 0.f);
    for (int t = c; t < T; t += 64) {
        float4 v = probs4[(size_t)t * 4 + e4];
        sum.x += v.x; sum.y += v.y; sum.z += v.z; sum.w += v.w;
    }
    s4[tid] = sum;
    __syncthreads();

    if (tid < 4) {
        float4 u = make_float4(0.f, 0.f, 0.f, 0.f);
        #pragma unroll
        for (int cc = 0; cc < 64; cc++) {
            float4 v = s4[cc * 4 + tid];
            u.x += v.x; u.y += v.y; u.z += v.z; u.w += v.w;
        }
        su4[tid] = u;
    }
    __syncthreads();

    if (tid == 0) {
        float invT = 1.0f / (float)T;
        float aux = 0.0f;
        #pragma unroll
        for (int q = 0; q < 4; q++) {
            float4 u = su4[q];
            float a = u.x * invT, b = u.y * invT, cc = u.z * invT, d = u.w * invT;
            aux += a * logf(a) + b * logf(b) + cc * logf(cc) + d * logf(d);
        }
        out_aux[0] = aux * (float)NUM_E;
    }
}

// ---------------------------------------------------------------------------
// Kernel 3: bias = w0*B[i0] + w1*B[i1]. Write-bound (262 MB stores).
// Block covers (500-float v-chunk) x (128 tokens). All 16 experts' chunk
// staged in 32 KB smem. Warp-per-token inner loop: lane-contiguous float4
// stores, no integer division.
// ---------------------------------------------------------------------------
#define CHUNK_F4 125          // 500 floats per expert per chunk
#define TOK_GRP  128

__global__ __launch_bounds__(256) void bias_kernel(
    const float* __restrict__ biases,
    float* __restrict__ out,
    int V)
{
    __shared__ float4 sB[NUM_E][CHUNK_F4];   // 32 KB
    __shared__ float4 smeta[TOK_GRP];        // 2 KB

    const int tid   = threadIdx.x;
    const int lane  = tid & 31;
    const int warp  = tid >> 5;
    const int Vf4   = V >> 2;                // 8000
    const int vbase = blockIdx.x * CHUNK_F4;
    const int tbase = blockIdx.y * TOK_GRP;

    const float4* __restrict__ bf4 = (const float4*)biases;
    float4* __restrict__ of4 = (float4*)out;

    for (int i = tid; i < NUM_E * CHUNK_F4; i += 256) {
        int e = i / CHUNK_F4, p = i - e * CHUNK_F4;
        sB[e][p] = bf4[(size_t)e * Vf4 + vbase + p];
    }
    if (tid < TOK_GRP) smeta[tid] = g_meta[tbase + tid];
    __syncthreads();

    // 8 warps, each sweeps tokens warp, warp+8, ... ; lanes cover the chunk.
    for (int t = warp; t < TOK_GRP; t += 8) {
        float4 m = smeta[t];
        const float w0 = m.x, w1 = m.y;
        const int i0 = __float_as_int(m.z);
        const int i1 = __float_as_int(m.w);
        float4* __restrict__ orow = &of4[(size_t)(tbase + t) * Vf4 + vbase];
        #pragma unroll 4
        for (int p = lane; p < CHUNK_F4; p += 32) {
            float4 a = sB[i0][p];
            float4 b = sB[i1][p];
            float4 r;
            r.x = w0 * a.x + w1 * b.x;
            r.y = w0 * a.y + w1 * b.y;
            r.z = w0 * a.z + w1 * b.z;
            r.w = w0 * a.w + w1 * b.w;
            orow[p] = r;
        }
    }
}

// ---------------------------------------------------------------------------
extern "C" void kernel_launch(void* const* d_in, const int* in_sizes, int n_in,
                              void* d_out, int out_size)
{
    const float* hidden = (const float*)d_in[0];
    const float* gate_w = (const float*)d_in[1];
    const float* biases = (const float*)d_in[2];
    float* out = (float*)d_out;

    const int H = in_sizes[1] / NUM_E;         // 2048
    const int T = in_sizes[0] / H;             // 2048
    const int V = in_sizes[2] / NUM_E;         // 32000

    // 1) gating: 4 tokens per block, full-chip grid
    gate_kernel<<<T / 4, 256>>>(hidden, gate_w, H);

    // 2) bias gather+blend (the big one)
    dim3 grid(V / (CHUNK_F4 * 4), T / TOK_GRP);   // (64, 16)
    bias_kernel<<<grid, 256>>>(biases, out, V);

    // 3) aux loss -> out[T*V]
    aux_kernel<<<1, 256>>>(out + (size_t)T * V, T);
}

// round 3
// speedup vs baseline: 1.2829x; 1.2819x over previous
#include <cuda_runtime.h>
#include <cuda_bf16.h>
#include <math.h>

// T=2048 tokens, H=2048 hidden, V=32000 vocab, E=16 experts, top-2.
// Inputs: hidden_states (T*H f32), gate_w (16*H f32), expert_biases (16*V f32).
// Output: bias (T*V f32) then aux_loss (1 f32).

#define NUM_E 16
#define MAX_T 8192

__device__ float  g_probs[MAX_T * NUM_E];   // softmax probs per token
__device__ float4 g_meta[MAX_T];            // (w0, w1, bitcast i0, bitcast i1)

// ---------------------------------------------------------------------------
// Kernel 1: gate logits + softmax + top-2.
// Block = 256 threads = 8 warps, 8 tokens. Warp w owns experts [4*(w&3), +4)
// over H-half (w>>2). acc[4 experts][8 tokens] = 32 regs/thread.
// Hidden float4s are shared across the 4 expert-groups via L1.
// ---------------------------------------------------------------------------
__global__ __launch_bounds__(256) void gate_kernel(
    const float* __restrict__ hidden,
    const float* __restrict__ gate_w,
    int H)
{
    const int tid  = threadIdx.x;
    const int lane = tid & 31;
    const int warp = tid >> 5;
    const int eg   = warp & 3;       // expert group: experts 4*eg .. 4*eg+3
    const int hh   = warp >> 1 >> 1; // H half (warp>>2)
    const int Hf4  = H >> 2;         // 512
    const int half = Hf4 >> 1;       // 256
    const int t0   = blockIdx.x * 8;

    const float4* __restrict__ hf4 = (const float4*)hidden;
    const float4* __restrict__ gf4 = (const float4*)gate_w;

    __shared__ float red[8][4][8];   // [warp][local expert][token]
    __shared__ float slog[8][NUM_E];

    float acc[4][8];
    #pragma unroll
    for (int e = 0; e < 4; e++)
        #pragma unroll
        for (int t = 0; t < 8; t++) acc[e][t] = 0.0f;

    const int ibeg = hh * half + lane;
    const int iend = hh * half + half;

    for (int i = ibeg; i < iend; i += 32) {
        float4 h[8];
        #pragma unroll
        for (int t = 0; t < 8; t++)
            h[t] = hf4[(size_t)(t0 + t) * Hf4 + i];
        #pragma unroll
        for (int e = 0; e < 4; e++) {
            float4 g = __ldg(&gf4[(size_t)(eg * 4 + e) * Hf4 + i]);
            #pragma unroll
            for (int t = 0; t < 8; t++)
                acc[e][t] += h[t].x*g.x + h[t].y*g.y + h[t].z*g.z + h[t].w*g.w;
        }
    }

    // intra-warp butterfly reduction (deterministic)
    #pragma unroll
    for (int e = 0; e < 4; e++) {
        #pragma unroll
        for (int t = 0; t < 8; t++) {
            float v = acc[e][t];
            v += __shfl_xor_sync(0xffffffffu, v, 16);
            v += __shfl_xor_sync(0xffffffffu, v, 8);
            v += __shfl_xor_sync(0xffffffffu, v, 4);
            v += __shfl_xor_sync(0xffffffffu, v, 2);
            v += __shfl_xor_sync(0xffffffffu, v, 1);
            if (lane == 0) red[warp][e][t] = v;
        }
    }
    __syncthreads();

    // combine the 2 H-halves: thread covers one (expert, token) cell
    if (tid < 128) {
        int e = tid >> 3, t = tid & 7;
        int g = e >> 2, el = e & 3;
        slog[t][e] = red[g][el][t] + red[g + 4][el][t];
    }
    __syncthreads();

    // per-token softmax + top-2
    if (tid < 8) {
        const int tok = t0 + tid;
        float l[NUM_E];
        float mx = -1e30f;
        #pragma unroll
        for (int e = 0; e < NUM_E; e++) { l[e] = slog[tid][e]; mx = fmaxf(mx, l[e]); }
        float sum = 0.0f;
        float p[NUM_E];
        #pragma unroll
        for (int e = 0; e < NUM_E; e++) { p[e] = expf(l[e] - mx); sum += p[e]; }
        float inv = 1.0f / sum;
        int   i0 = 0, i1 = -1;
        float p0 = -1.0f, p1 = -1.0f;
        #pragma unroll
        for (int e = 0; e < NUM_E; e++) {
            float pe = p[e] * inv;
            g_probs[(size_t)tok * NUM_E + e] = pe;
            if (pe > p0)      { p1 = p0; i1 = i0; p0 = pe; i0 = e; }
            else if (pe > p1) { p1 = pe; i1 = e; }
        }
        float s2 = p0 + p1;
        float4 m;
        m.x = p0 / s2;
        m.y = p1 / s2;
        m.z = __int_as_float(i0);
        m.w = __int_as_float(i1);
        g_meta[tok] = m;
    }
}

// ---------------------------------------------------------------------------
// Kernel 2: aux loss. Single block, float4 coalesced, deterministic.
// ---------------------------------------------------------------------------
__global__ __launch_bounds__(256) void aux_kernel(float* __restrict__ out_aux, int T)
{
    __shared__ float4 s4[256];
    __shared__ float4 su4[4];
    const int tid = threadIdx.x;
    const int e4  = tid & 3;
    const int c   = tid >> 2;

    const float4* __restrict__ probs4 = (const float4*)g_probs;

    float4 sum = make_float4(0.f, 0.f, 0.f, 0.f);
    for (int t = c; t < T; t += 64) {
        float4 v = probs4[(size_t)t * 4 + e4];
        sum.x += v.x; sum.y += v.y; sum.z += v.z; sum.w += v.w;
    }
    s4[tid] = sum;
    __syncthreads();

    if (tid < 4) {
        float4 u = make_float4(0.f, 0.f, 0.f, 0.f);
        #pragma unroll
        for (int cc = 0; cc < 64; cc++) {
            float4 v = s4[cc * 4 + tid];
            u.x += v.x; u.y += v.y; u.z += v.z; u.w += v.w;
        }
        su4[tid] = u;
    }
    __syncthreads();

    if (tid == 0) {
        float invT = 1.0f / (float)T;
        float aux = 0.0f;
        #pragma unroll
        for (int q = 0; q < 4; q++) {
            float4 u = su4[q];
            float a = u.x * invT, b = u.y * invT, cc = u.z * invT, d = u.w * invT;
            aux += a * logf(a) + b * logf(b) + cc * logf(cc) + d * logf(d);
        }
        out_aux[0] = aux * (float)NUM_E;
    }
}

// ---------------------------------------------------------------------------
// Kernel 3: bias = w0*B[i0] + w1*B[i1]. 262 MB of stores.
// CHUNK = 512 floats = 2048 B = 16 whole L2 lines -> every CTA writes full
// sectors/lines (no DRAM read-modify-write). grid.x = 63 (62 full + 1 tail of
// 256 floats, also line-aligned). Streaming stores (__stcs): output is never
// re-read, keep it out of L2's working set.
// ---------------------------------------------------------------------------
#define CHUNK_F4 128          // 512 floats = 2048 B per expert per chunk
#define TOK_GRP  128

__global__ __launch_bounds__(256) void bias_kernel(
    const float* __restrict__ biases,
    float* __restrict__ out,
    int V)
{
    __shared__ float4 sB[NUM_E][CHUNK_F4];   // 32 KB
    __shared__ float4 smeta[TOK_GRP];        // 2 KB

    const int tid   = threadIdx.x;
    const int lane  = tid & 31;
    const int warp  = tid >> 5;
    const int Vf4   = V >> 2;                       // 8000
    const int vbase = blockIdx.x * CHUNK_F4;        // f4 offset, 2048B-aligned
    const int clen  = min(CHUNK_F4, Vf4 - vbase);   // 128 or 64 (tail)
    const int tbase = blockIdx.y * TOK_GRP;

    const float4* __restrict__ bf4 = (const float4*)biases;
    float4* __restrict__ of4 = (float4*)out;

    // stage all 16 experts' chunk
    for (int i = tid; i < NUM_E * CHUNK_F4; i += 256) {
        int e = i >> 7, p = i & (CHUNK_F4 - 1);
        if (p < clen) sB[e][p] = bf4[(size_t)e * Vf4 + vbase + p];
    }
    if (tid < TOK_GRP) smeta[tid] = g_meta[tbase + tid];
    __syncthreads();

    // warp-per-token, lane-contiguous 16B stores (512B/warp bursts)
    for (int t = warp; t < TOK_GRP; t += 8) {
        float4 m = smeta[t];
        const float w0 = m.x, w1 = m.y;
        const int i0 = __float_as_int(m.z);
        const int i1 = __float_as_int(m.w);
        float4* __restrict__ orow = &of4[(size_t)(tbase + t) * Vf4 + vbase];
        #pragma unroll 4
        for (int p = lane; p < clen; p += 32) {
            float4 a = sB[i0][p];
            float4 b = sB[i1][p];
            float4 r;
            r.x = w0 * a.x + w1 * b.x;
            r.y = w0 * a.y + w1 * b.y;
            r.z = w0 * a.z + w1 * b.z;
            r.w = w0 * a.w + w1 * b.w;
            __stcs(&orow[p], r);
        }
    }
}

// ---------------------------------------------------------------------------
extern "C" void kernel_launch(void* const* d_in, const int* in_sizes, int n_in,
                              void* d_out, int out_size)
{
    const float* hidden = (const float*)d_in[0];
    const float* gate_w = (const float*)d_in[1];
    const float* biases = (const float*)d_in[2];
    float* out = (float*)d_out;

    const int H = in_sizes[1] / NUM_E;         // 2048
    const int T = in_sizes[0] / H;             // 2048
    const int V = in_sizes[2] / NUM_E;         // 32000

    // 1) gating: 8 tokens per block
    gate_kernel<<<T / 8, 256>>>(hidden, gate_w, H);

    // 2) bias gather+blend: 63 line-aligned v-chunks x 16 token groups
    const int nchunks = (V / 4 + CHUNK_F4 - 1) / CHUNK_F4;   // 63
    dim3 grid(nchunks, T / TOK_GRP);
    bias_kernel<<<grid, 256>>>(biases, out, V);

    // 3) aux loss -> out[T*V]
    aux_kernel<<<1, 256>>>(out + (size_t)T * V, T);
}